// round 10
// baseline (speedup 1.0000x reference)
#include <cuda_runtime.h>

#define WD 512
#define RB 8
#define NBATCH 4
#define ROWF 512
#define NCC_BLOCKS 512
#define GRAD_BLOCKS 64
#define TOTAL_BLOCKS (NCC_BLOCKS + GRAD_BLOCKS)
#define STAGE_FLOATS (RB * 5 * ROWF)           // 20480 floats = 81920 B (single buffer)
#define SMEM_BYTES (STAGE_FLOATS * 4)

// [0],[1]: cc sums per channel; [2]: sum dx^2; [3]: sum dy^2
__device__ double g_acc[4];
__device__ unsigned int g_count;

__global__ __launch_bounds__(512, 2) void fused_kernel(const float* __restrict__ I,
                                                       const float* __restrict__ J,
                                                       const float* __restrict__ dvf,
                                                       int n_dvf,
                                                       float* __restrict__ out) {
    extern __shared__ __align__(16) float stage[];   // [RB][5][ROWF]
    __shared__ float red[16];
    __shared__ float red2[16];
    __shared__ bool is_last;

    const int t = threadIdx.x;
    const int blk = blockIdx.x;

    if (blk < NCC_BLOCKS) {
        // ───────────────────────── NCC block ─────────────────────────
        const int img = blk >> 4;       // 16 bands per image, 32 images
        const int band = blk & 15;
        const int r0 = band * 32;
        const size_t base = (size_t)img * (WD * WD);
        const float* __restrict__ Ip = I + base;
        const float* __restrict__ Jp = J + base;

        // prime: column sums over rows [r0-4, r0+3]
        float cs0 = 0.f, cs1 = 0.f, cs2 = 0.f, cs3 = 0.f, cs4 = 0.f;
#pragma unroll
        for (int k = 0; k < 8; k++) {
            const int r = r0 - 4 + k;
            if (r >= 0) {
                float a = Ip[r * WD + t];
                float b = Jp[r * WD + t];
                cs0 += a; cs1 += b; cs2 += a * a; cs3 += b * b; cs4 += a * b;
            }
        }

        float acc = 0.f;
        const int rsB = t >> 6;         // staged row 0..7
        const int seg = t & 63;         // 8-col run: cols [seg*8, seg*8+8)
        const int fb = seg * 2;         // float4 block index of run start
        const float inv81 = 1.0f / 81.0f;
        const bool hasL = (seg > 0);
        const bool hasR = (seg < 63);
        const float4 z4 = make_float4(0.f, 0.f, 0.f, 0.f);

        for (int b = 0; b < NBATCH; b++) {
            const int rbase = r0 + b * RB;

            // ── phase A: slide vertical sums over 8 rows, stage column sums ──
#pragma unroll
            for (int rr = 0; rr < RB; rr++) {
                const int r = rbase + rr;
                float a = 0.f, bb = 0.f;
                if (r + 4 < WD) { a = Ip[(r + 4) * WD + t]; bb = Jp[(r + 4) * WD + t]; }
                float c = 0.f, d = 0.f;
                if (r - 4 >= 0) { c = Ip[(r - 4) * WD + t]; d = Jp[(r - 4) * WD + t]; }
                cs0 += a; cs1 += bb; cs2 += a * a; cs3 += bb * bb; cs4 += a * bb;
                float* rowp = stage + (size_t)(rr * 5) * ROWF + t;
                rowp[0 * ROWF] = cs0;
                rowp[1 * ROWF] = cs1;
                rowp[2 * ROWF] = cs2;
                rowp[3 * ROWF] = cs3;
                rowp[4 * ROWF] = cs4;
                cs0 -= c; cs1 -= d; cs2 -= c * c; cs3 -= d * d; cs4 -= c * d;
            }
            __syncthreads();            // staged sums ready

            // ── phase B: horizontal 9-sums over 16-float window (4x LDS.128) ──
            // window for pixel c0+i is cols [c0+i-4, c0+i+4]; blocks fb-1..fb+2.
            // out-of-range blocks are exactly zero (zero-padded convolution).
            float S[5][8];
#pragma unroll
            for (int q = 0; q < 5; q++) {
                const float4* row4 = (const float4*)(stage + (size_t)(rsB * 5 + q) * ROWF);
                float4 A = hasL ? row4[fb - 1] : z4;
                float4 B = row4[fb];
                float4 C = row4[fb + 1];
                float4 D = hasR ? row4[fb + 2] : z4;
                float s = A.x + A.y + A.z + A.w + B.x + B.y + B.z + B.w + C.x;
                S[q][0] = s;
                s += C.y - A.x; S[q][1] = s;
                s += C.z - A.y; S[q][2] = s;
                s += C.w - A.z; S[q][3] = s;
                s += D.x - A.w; S[q][4] = s;
                s += D.y - B.x; S[q][5] = s;
                s += D.z - B.y; S[q][6] = s;
                s += D.w - B.z; S[q][7] = s;
            }
#pragma unroll
            for (int i = 0; i < 8; i++) {
                float sI = S[0][i], sJ = S[1][i];
                float sII = S[2][i], sJJ = S[3][i], sIJ = S[4][i];
                float cross = sIJ - sI * sJ * inv81;
                float Iv = sII - sI * sI * inv81;
                float Jv = sJJ - sJ * sJ * inv81;
                acc += __fdividef(cross * cross, Iv * Jv + 1e-5f);
            }
            __syncthreads();            // stage free for next phase A
        }

        // block reduction
#pragma unroll
        for (int d = 16; d > 0; d >>= 1) acc += __shfl_down_sync(0xffffffffu, acc, d);
        if ((t & 31) == 0) red[t >> 5] = acc;
        __syncthreads();
        if (t < 32) {
            float v = (t < 16) ? red[t] : 0.f;
#pragma unroll
            for (int d = 8; d > 0; d >>= 1) v += __shfl_down_sync(0xffffffffu, v, d);
            if (t == 0) atomicAdd(&g_acc[img & 1], (double)v);
        }
    } else {
        // ───────────────────────── grad block ─────────────────────────
        float adx = 0.f, ady = 0.f;
        const int gb = blk - NCC_BLOCKS;
        for (int idx = gb * 512 + t; idx < n_dvf; idx += GRAD_BLOCKS * 512) {
            const int hw = idx & 65535;          // position within one 256x256 map
            const float c = dvf[idx];
            if ((hw & 255) != 255) { float d = dvf[idx + 1] - c; adx += d * d; }
            if (hw < 65280)        { float d = dvf[idx + 256] - c; ady += d * d; }
        }
#pragma unroll
        for (int d = 16; d > 0; d >>= 1) {
            adx += __shfl_down_sync(0xffffffffu, adx, d);
            ady += __shfl_down_sync(0xffffffffu, ady, d);
        }
        if ((t & 31) == 0) { red[t >> 5] = adx; red2[t >> 5] = ady; }
        __syncthreads();
        if (t < 32) {
            float x = (t < 16) ? red[t] : 0.f;
            float y = (t < 16) ? red2[t] : 0.f;
#pragma unroll
            for (int d = 4; d > 0; d >>= 1) {
                x += __shfl_down_sync(0xffffffffu, x, d);
                y += __shfl_down_sync(0xffffffffu, y, d);
            }
            x += __shfl_down_sync(0xffffffffu, x, 8);
            y += __shfl_down_sync(0xffffffffu, y, 8);
            if (t == 0) {
                atomicAdd(&g_acc[2], (double)x);
                atomicAdd(&g_acc[3], (double)y);
            }
        }
    }

    // ───────────────── last-block finalize (graph-replay safe) ─────────────────
    __threadfence();
    if (t == 0) {
        unsigned int prev = atomicAdd(&g_count, 1u);
        is_last = (prev == (unsigned int)(TOTAL_BLOCKS - 1));
    }
    __syncthreads();
    if (is_last && t == 0) {
        // ncc = -(m0 + m1)/(C-1), C=2; m_c = sum_c / (B*H*W)
        double ncc = -(g_acc[0] + g_acc[1]) / (16.0 * 512.0 * 512.0);
        // grad = 0.01 * ((mean(dx^2)+mean(dy^2))/2 * 2.0)
        double Nd = 16.0 * 2.0 * 256.0 * 255.0;
        double grad = 0.01 * (g_acc[2] / Nd + g_acc[3] / Nd);
        out[0] = (float)(ncc + grad);
        out[1] = (float)ncc;
        out[2] = (float)grad;
        g_acc[0] = 0.0; g_acc[1] = 0.0; g_acc[2] = 0.0; g_acc[3] = 0.0;
        g_count = 0u;
    }
}

extern "C" void kernel_launch(void* const* d_in, const int* in_sizes, int n_in,
                              void* d_out, int out_size) {
    const float* y_true = (const float*)d_in[0];
    const float* y_pred = (const float*)d_in[1];
    const float* dvf    = (const float*)d_in[2];
    float* out = (float*)d_out;
    const int n_dvf = in_sizes[2];

    cudaFuncSetAttribute(fused_kernel, cudaFuncAttributeMaxDynamicSharedMemorySize,
                         SMEM_BYTES);
    fused_kernel<<<TOTAL_BLOCKS, 512, SMEM_BYTES>>>(y_true, y_pred, dvf, n_dvf, out);
}

// round 11
// speedup vs baseline: 1.1916x; 1.1916x over previous
#include <cuda_runtime.h>

#define WD 512
#define RB 4
#define NBATCH 8
#define ROWF 520            // 4 pad + 512 + 4 pad
#define NCC_BLOCKS 512
#define GRAD_BLOCKS 64
#define TOTAL_BLOCKS (NCC_BLOCKS + GRAD_BLOCKS)
#define SMEM_BYTES (2 * RB * 5 * ROWF * 4)   // 83200 B, double-buffered

// [0],[1]: cc sums per channel; [2]: sum dx^2; [3]: sum dy^2
__device__ double g_acc[4];
__device__ unsigned int g_count;

__global__ __launch_bounds__(512, 2) void fused_kernel(const float* __restrict__ I,
                                                       const float* __restrict__ J,
                                                       const float* __restrict__ dvf,
                                                       int n_dvf,
                                                       float* __restrict__ out) {
    extern __shared__ __align__(16) float dyn[];   // [2][RB][5][ROWF]
    __shared__ float red[16];
    __shared__ float red2[16];
    __shared__ bool is_last;

    const int t = threadIdx.x;
    const int blk = blockIdx.x;

    if (blk < NCC_BLOCKS) {
        // ───────────────────────── NCC block ─────────────────────────
        const int img = blk >> 4;      // 16 bands per image, 32 images
        const int band = blk & 15;
        const int r0 = band * 32;
        const size_t base = (size_t)img * (WD * WD);
        const float* __restrict__ Ip = I + base;
        const float* __restrict__ Jp = J + base;

        // zero the horizontal padding (cols 0..3, 516..519) in BOTH stage buffers
        if (t < 4) {
#pragma unroll
            for (int bu = 0; bu < 2; bu++)
#pragma unroll
                for (int rr = 0; rr < RB; rr++)
#pragma unroll
                    for (int q = 0; q < 5; q++) {
                        float* row = dyn + (size_t)(((bu * RB) + rr) * 5 + q) * ROWF;
                        row[t] = 0.0f;
                        row[516 + t] = 0.0f;
                    }
        }

        // vertical sliding column sums: invariant at loop top = rows [r-4, r+3]
        float cs0 = 0.f, cs1 = 0.f, cs2 = 0.f, cs3 = 0.f, cs4 = 0.f;
#pragma unroll
        for (int k = 0; k < 8; k++) {
            int rr = r0 - 4 + k;
            if (rr >= 0) {
                float a = Ip[rr * WD + t];
                float b = Jp[rr * WD + t];
                cs0 += a; cs1 += b; cs2 += a * a; cs3 += b * b; cs4 += a * b;
            }
        }

        // phase A: stage RB rows of column sums into buffer `buf`
        auto phaseA = [&](int buf, int rbase) {
#pragma unroll
            for (int rr = 0; rr < RB; rr++) {
                const int r = rbase + rr;
                float a = 0.f, b = 0.f;
                if (r + 4 < WD) { a = Ip[(r + 4) * WD + t]; b = Jp[(r + 4) * WD + t]; }
                cs0 += a; cs1 += b; cs2 += a * a; cs3 += b * b; cs4 += a * b;
                float* rowp = dyn + (size_t)((buf * RB + rr) * 5) * ROWF + 4 + t;
                rowp[0 * ROWF] = cs0;
                rowp[1 * ROWF] = cs1;
                rowp[2 * ROWF] = cs2;
                rowp[3 * ROWF] = cs3;
                rowp[4 * ROWF] = cs4;
                float c = 0.f, d = 0.f;
                if (r - 4 >= 0) { c = Ip[(r - 4) * WD + t]; d = Jp[(r - 4) * WD + t]; }
                cs0 -= c; cs1 -= d; cs2 -= c * c; cs3 -= d * d; cs4 -= c * d;
            }
        };

        float acc = 0.f;
        const int rsB = t >> 7;      // which of the 4 staged rows
        const int seg = t & 127;     // 4-column run: cols [seg*4, seg*4+4)
        const float inv81 = 1.0f / 81.0f;

        // phase B: horizontal 9-sums + cc for buffer `buf`.
        // The 4 per-pixel divides are batched into ONE __fdividef:
        //   sum_i n_i/d_i = ((n0 d1 + n1 d0)(d2 d3) + (n2 d3 + n3 d2)(d0 d1)) / (d0 d1 d2 d3)
        auto phaseB = [&](int buf) {
            float S[5][4];
#pragma unroll
            for (int q = 0; q < 5; q++) {
                const float4* row4 =
                    (const float4*)(dyn + (size_t)((buf * RB + rsB) * 5 + q) * ROWF);
                float4 A = row4[seg], B = row4[seg + 1], C = row4[seg + 2];
                float s = A.x + A.y + A.z + A.w + B.x + B.y + B.z + B.w + C.x;
                S[q][0] = s;
                s += C.y - A.x; S[q][1] = s;
                s += C.z - A.y; S[q][2] = s;
                s += C.w - A.z; S[q][3] = s;
            }
            float num[4], den[4];
#pragma unroll
            for (int i = 0; i < 4; i++) {
                float sI = S[0][i], sJ = S[1][i];
                float sII = S[2][i], sJJ = S[3][i], sIJ = S[4][i];
                float cross = sIJ - sI * sJ * inv81;
                float Iv = sII - sI * sI * inv81;
                float Jv = sJJ - sJ * sJ * inv81;
                num[i] = cross * cross;
                den[i] = Iv * Jv + 1e-5f;
            }
            float d01 = den[0] * den[1];
            float d23 = den[2] * den[3];
            float n01 = num[0] * den[1] + num[1] * den[0];
            float n23 = num[2] * den[3] + num[3] * den[2];
            acc += __fdividef(n01 * d23 + n23 * d01, d01 * d23);
        };

        __syncthreads();              // padding visible
        phaseA(0, r0);
        __syncthreads();              // buf0 ready

        for (int b = 0; b < NBATCH; b++) {
            if (b + 1 < NBATCH) phaseA((b + 1) & 1, r0 + (b + 1) * RB);  // overlaps B(b)
            phaseB(b & 1);
            __syncthreads();          // publishes A(b+1), protects buf reuse
        }

        // block reduction
#pragma unroll
        for (int d = 16; d > 0; d >>= 1) acc += __shfl_down_sync(0xffffffffu, acc, d);
        if ((t & 31) == 0) red[t >> 5] = acc;
        __syncthreads();
        if (t < 32) {
            float v = (t < 16) ? red[t] : 0.f;
#pragma unroll
            for (int d = 8; d > 0; d >>= 1) v += __shfl_down_sync(0xffffffffu, v, d);
            if (t == 0) atomicAdd(&g_acc[img & 1], (double)v);
        }
    } else {
        // ───────────────────────── grad block ─────────────────────────
        float adx = 0.f, ady = 0.f;
        const int gb = blk - NCC_BLOCKS;
        for (int idx = gb * 512 + t; idx < n_dvf; idx += GRAD_BLOCKS * 512) {
            const int hw = idx & 65535;           // position within one 256x256 map
            const float c = dvf[idx];
            if ((hw & 255) != 255) { float d = dvf[idx + 1] - c; adx += d * d; }
            if (hw < 65280)        { float d = dvf[idx + 256] - c; ady += d * d; }
        }
#pragma unroll
        for (int d = 16; d > 0; d >>= 1) {
            adx += __shfl_down_sync(0xffffffffu, adx, d);
            ady += __shfl_down_sync(0xffffffffu, ady, d);
        }
        if ((t & 31) == 0) { red[t >> 5] = adx; red2[t >> 5] = ady; }
        __syncthreads();
        if (t < 32) {
            float x = (t < 16) ? red[t] : 0.f;
            float y = (t < 16) ? red2[t] : 0.f;
#pragma unroll
            for (int d = 8; d > 0; d >>= 1) {
                x += __shfl_down_sync(0xffffffffu, x, d);
                y += __shfl_down_sync(0xffffffffu, y, d);
            }
            if (t == 0) {
                atomicAdd(&g_acc[2], (double)x);
                atomicAdd(&g_acc[3], (double)y);
            }
        }
    }

    // ───────────────── last-block finalize (graph-replay safe) ─────────────────
    __threadfence();
    if (t == 0) {
        unsigned int prev = atomicAdd(&g_count, 1u);
        is_last = (prev == (unsigned int)(TOTAL_BLOCKS - 1));
    }
    __syncthreads();
    if (is_last && t == 0) {
        // ncc = -(m0 + m1)/(C-1), C=2; m_c = sum_c / (B*H*W)
        double ncc = -(g_acc[0] + g_acc[1]) / (16.0 * 512.0 * 512.0);
        // grad = 0.01 * ((mean(dx^2)+mean(dy^2))/2 * 2.0)
        double Nd = 16.0 * 2.0 * 256.0 * 255.0;
        double grad = 0.01 * (g_acc[2] / Nd + g_acc[3] / Nd);
        out[0] = (float)(ncc + grad);
        out[1] = (float)ncc;
        out[2] = (float)grad;
        g_acc[0] = 0.0; g_acc[1] = 0.0; g_acc[2] = 0.0; g_acc[3] = 0.0;
        g_count = 0u;
    }
}

extern "C" void kernel_launch(void* const* d_in, const int* in_sizes, int n_in,
                              void* d_out, int out_size) {
    const float* y_true = (const float*)d_in[0];
    const float* y_pred = (const float*)d_in[1];
    const float* dvf    = (const float*)d_in[2];
    float* out = (float*)d_out;
    const int n_dvf = in_sizes[2];

    cudaFuncSetAttribute(fused_kernel, cudaFuncAttributeMaxDynamicSharedMemorySize,
                         SMEM_BYTES);
    fused_kernel<<<TOTAL_BLOCKS, 512, SMEM_BYTES>>>(y_true, y_pred, dvf, n_dvf, out);
}

// round 12
// speedup vs baseline: 1.3322x; 1.1180x over previous
#include <cuda_runtime.h>

#define WD 512
#define BAND 16
#define RB 2
#define NBATCH 8
#define ROWF 520            // 4 pad + 512 + 4 pad
#define NCC_BLOCKS 1024
#define GRAD_BLOCKS 128
#define TOTAL_BLOCKS (NCC_BLOCKS + GRAD_BLOCKS)
#define SMEM_BYTES (2 * RB * 5 * ROWF * 4)   // 41600 B, double-buffered

// [0],[1]: cc sums per channel; [2]: sum dx^2; [3]: sum dy^2
__device__ double g_acc[4];
__device__ unsigned int g_count;

__global__ __launch_bounds__(256, 4) void fused_kernel(const float* __restrict__ I,
                                                       const float* __restrict__ J,
                                                       const float* __restrict__ dvf,
                                                       int n_dvf,
                                                       float* __restrict__ out) {
    extern __shared__ __align__(16) float dyn[];   // [2][RB][5][ROWF]
    __shared__ float red[8];
    __shared__ float red2[8];
    __shared__ bool is_last;

    const int t = threadIdx.x;
    const int blk = blockIdx.x;

    if (blk < NCC_BLOCKS) {
        // ───────────────────────── NCC block ─────────────────────────
        const int img = blk >> 5;       // 32 bands per image, 32 images
        const int band = blk & 31;
        const int r0 = band * BAND;
        const size_t base = (size_t)img * (WD * WD);
        const float* __restrict__ Ip = I + base;
        const float* __restrict__ Jp = J + base;

        // zero the horizontal padding (cols 0..3, 516..519) in BOTH stage buffers
        if (t < 4) {
#pragma unroll
            for (int bu = 0; bu < 2; bu++)
#pragma unroll
                for (int rr = 0; rr < RB; rr++)
#pragma unroll
                    for (int q = 0; q < 5; q++) {
                        float* row = dyn + (size_t)(((bu * RB) + rr) * 5 + q) * ROWF;
                        row[t] = 0.0f;
                        row[516 + t] = 0.0f;
                    }
        }

        // each thread owns columns 2t and 2t+1 (float2 loads/stores)
        const int c0 = 2 * t;
        float ca0 = 0.f, ca1 = 0.f, ca2 = 0.f, ca3 = 0.f, ca4 = 0.f;   // col 2t
        float cb0 = 0.f, cb1 = 0.f, cb2 = 0.f, cb3 = 0.f, cb4 = 0.f;   // col 2t+1
#pragma unroll
        for (int k = 0; k < 8; k++) {
            int r = r0 - 4 + k;
            if (r >= 0) {
                float2 a = *(const float2*)(Ip + r * WD + c0);
                float2 b = *(const float2*)(Jp + r * WD + c0);
                ca0 += a.x; ca1 += b.x; ca2 += a.x * a.x; ca3 += b.x * b.x; ca4 += a.x * b.x;
                cb0 += a.y; cb1 += b.y; cb2 += a.y * a.y; cb3 += b.y * b.y; cb4 += a.y * b.y;
            }
        }

        // phase A: stage RB rows of column sums into buffer `buf`
        auto phaseA = [&](int buf, int rbase) {
#pragma unroll
            for (int rr = 0; rr < RB; rr++) {
                const int r = rbase + rr;
                float2 a = make_float2(0.f, 0.f), b = make_float2(0.f, 0.f);
                if (r + 4 < WD) {
                    a = *(const float2*)(Ip + (r + 4) * WD + c0);
                    b = *(const float2*)(Jp + (r + 4) * WD + c0);
                }
                ca0 += a.x; ca1 += b.x; ca2 += a.x * a.x; ca3 += b.x * b.x; ca4 += a.x * b.x;
                cb0 += a.y; cb1 += b.y; cb2 += a.y * a.y; cb3 += b.y * b.y; cb4 += a.y * b.y;
                float* rowp = dyn + (size_t)((buf * RB + rr) * 5) * ROWF + 4 + c0;
                *(float2*)(rowp + 0 * ROWF) = make_float2(ca0, cb0);
                *(float2*)(rowp + 1 * ROWF) = make_float2(ca1, cb1);
                *(float2*)(rowp + 2 * ROWF) = make_float2(ca2, cb2);
                *(float2*)(rowp + 3 * ROWF) = make_float2(ca3, cb3);
                *(float2*)(rowp + 4 * ROWF) = make_float2(ca4, cb4);
                float2 c = make_float2(0.f, 0.f), d = make_float2(0.f, 0.f);
                if (r - 4 >= 0) {
                    c = *(const float2*)(Ip + (r - 4) * WD + c0);
                    d = *(const float2*)(Jp + (r - 4) * WD + c0);
                }
                ca0 -= c.x; ca1 -= d.x; ca2 -= c.x * c.x; ca3 -= d.x * d.x; ca4 -= c.x * d.x;
                cb0 -= c.y; cb1 -= d.y; cb2 -= c.y * c.y; cb3 -= d.y * d.y; cb4 -= c.y * d.y;
            }
        };

        float acc = 0.f;
        const int rsB = t >> 7;      // which of the 2 staged rows
        const int seg = t & 127;     // 4-column run: cols [seg*4, seg*4+4)
        const float inv81 = 1.0f / 81.0f;

        // phase B: horizontal 9-sums + cc; 4 divides batched into one.
        auto phaseB = [&](int buf) {
            float S[5][4];
#pragma unroll
            for (int q = 0; q < 5; q++) {
                const float4* row4 =
                    (const float4*)(dyn + (size_t)((buf * RB + rsB) * 5 + q) * ROWF);
                float4 A = row4[seg], B = row4[seg + 1], C = row4[seg + 2];
                float s = A.x + A.y + A.z + A.w + B.x + B.y + B.z + B.w + C.x;
                S[q][0] = s;
                s += C.y - A.x; S[q][1] = s;
                s += C.z - A.y; S[q][2] = s;
                s += C.w - A.z; S[q][3] = s;
            }
            float num[4], den[4];
#pragma unroll
            for (int i = 0; i < 4; i++) {
                float sI = S[0][i], sJ = S[1][i];
                float sII = S[2][i], sJJ = S[3][i], sIJ = S[4][i];
                float cross = sIJ - sI * sJ * inv81;
                float Iv = sII - sI * sI * inv81;
                float Jv = sJJ - sJ * sJ * inv81;
                num[i] = cross * cross;
                den[i] = Iv * Jv + 1e-5f;
            }
            float d01 = den[0] * den[1];
            float d23 = den[2] * den[3];
            float n01 = num[0] * den[1] + num[1] * den[0];
            float n23 = num[2] * den[3] + num[3] * den[2];
            acc += __fdividef(n01 * d23 + n23 * d01, d01 * d23);
        };

        __syncthreads();              // padding visible
        phaseA(0, r0);
        __syncthreads();              // buf0 ready

        for (int b = 0; b < NBATCH; b++) {
            if (b + 1 < NBATCH) phaseA((b + 1) & 1, r0 + (b + 1) * RB);  // overlaps B(b)
            phaseB(b & 1);
            __syncthreads();          // publishes A(b+1), protects buf reuse
        }

        // block reduction (8 warps)
#pragma unroll
        for (int d = 16; d > 0; d >>= 1) acc += __shfl_down_sync(0xffffffffu, acc, d);
        if ((t & 31) == 0) red[t >> 5] = acc;
        __syncthreads();
        if (t < 32) {
            float v = (t < 8) ? red[t] : 0.f;
#pragma unroll
            for (int d = 4; d > 0; d >>= 1) v += __shfl_down_sync(0xffffffffu, v, d);
            if (t == 0) atomicAdd(&g_acc[img & 1], (double)v);
        }
    } else {
        // ───────────────────────── grad block ─────────────────────────
        float adx = 0.f, ady = 0.f;
        const int gb = blk - NCC_BLOCKS;
        for (int idx = gb * 256 + t; idx < n_dvf; idx += GRAD_BLOCKS * 256) {
            const int hw = idx & 65535;           // position within one 256x256 map
            const float c = dvf[idx];
            if ((hw & 255) != 255) { float d = dvf[idx + 1] - c; adx += d * d; }
            if (hw < 65280)        { float d = dvf[idx + 256] - c; ady += d * d; }
        }
#pragma unroll
        for (int d = 16; d > 0; d >>= 1) {
            adx += __shfl_down_sync(0xffffffffu, adx, d);
            ady += __shfl_down_sync(0xffffffffu, ady, d);
        }
        if ((t & 31) == 0) { red[t >> 5] = adx; red2[t >> 5] = ady; }
        __syncthreads();
        if (t < 32) {
            float x = (t < 8) ? red[t] : 0.f;
            float y = (t < 8) ? red2[t] : 0.f;
#pragma unroll
            for (int d = 4; d > 0; d >>= 1) {
                x += __shfl_down_sync(0xffffffffu, x, d);
                y += __shfl_down_sync(0xffffffffu, y, d);
            }
            if (t == 0) {
                atomicAdd(&g_acc[2], (double)x);
                atomicAdd(&g_acc[3], (double)y);
            }
        }
    }

    // ───────────────── last-block finalize (graph-replay safe) ─────────────────
    __threadfence();
    if (t == 0) {
        unsigned int prev = atomicAdd(&g_count, 1u);
        is_last = (prev == (unsigned int)(TOTAL_BLOCKS - 1));
    }
    __syncthreads();
    if (is_last && t == 0) {
        // ncc = -(m0 + m1)/(C-1), C=2; m_c = sum_c / (B*H*W)
        double ncc = -(g_acc[0] + g_acc[1]) / (16.0 * 512.0 * 512.0);
        // grad = 0.01 * ((mean(dx^2)+mean(dy^2))/2 * 2.0)
        double Nd = 16.0 * 2.0 * 256.0 * 255.0;
        double grad = 0.01 * (g_acc[2] / Nd + g_acc[3] / Nd);
        out[0] = (float)(ncc + grad);
        out[1] = (float)ncc;
        out[2] = (float)grad;
        g_acc[0] = 0.0; g_acc[1] = 0.0; g_acc[2] = 0.0; g_acc[3] = 0.0;
        g_count = 0u;
    }
}

extern "C" void kernel_launch(void* const* d_in, const int* in_sizes, int n_in,
                              void* d_out, int out_size) {
    const float* y_true = (const float*)d_in[0];
    const float* y_pred = (const float*)d_in[1];
    const float* dvf    = (const float*)d_in[2];
    float* out = (float*)d_out;
    const int n_dvf = in_sizes[2];

    cudaFuncSetAttribute(fused_kernel, cudaFuncAttributeMaxDynamicSharedMemorySize,
                         SMEM_BYTES);
    fused_kernel<<<TOTAL_BLOCKS, 256, SMEM_BYTES>>>(y_true, y_pred, dvf, n_dvf, out);
}